// round 15
// baseline (speedup 1.0000x reference)
#include <cuda_runtime.h>
#include <cuda_bf16.h>

// ConvKB scoring, f32x2-packed, warp-pair d-split, EB=4.
//   score[e] = sum_{c,d} relu(w0_c*h[row,d] + w1_c*h[col,d] + w2_c*g[t,d] + cb_c) * lw[c,d] + lb
// E=50000, D=128, C=32.
//
// Two warps (a "pair") co-process EB=4 edges: warp parity p owns d-half
// [p*64, p*64+64); each lane holds 2 floats (one f32x2) per embedding per edge.
// Embedding regs: 12 ull (was 24 at EB=4 full-d) -> fits 64-reg cap, 4 CTAs/SM.
// Channel-outer loop amortizes conv/lin LDS over 4 edges. Partial sums combined
// across the pair via named barrier + double-buffered smem.
// Grid sized so every pair does exactly ceil-uniform full iterations (no tail).

#define D 128
#define C 32
#define EB 4
#define WARPS_PER_BLOCK 8           // 4 pairs
#define PAIRS_PER_BLOCK 4
#define THREADS 256
#define MAX_BLOCKS (148 * 4)        // 4 CTAs/SM capacity

typedef unsigned long long ull;

__device__ __forceinline__ ull pack2(float lo, float hi) {
    ull r; asm("mov.b64 %0,{%1,%2};" : "=l"(r) : "f"(lo), "f"(hi)); return r;
}
__device__ __forceinline__ float2 unpack2(ull x) {
    float2 f; asm("mov.b64 {%0,%1},%2;" : "=f"(f.x), "=f"(f.y) : "l"(x)); return f;
}
__device__ __forceinline__ ull fma2(ull a, ull b, ull c) {
    ull d; asm("fma.rn.f32x2 %0,%1,%2,%3;" : "=l"(d) : "l"(a), "l"(b), "l"(c)); return d;
}
__device__ __forceinline__ ull relu2(ull x) {
    asm("{\n\t"
        ".reg .f32 lo, hi;\n\t"
        "mov.b64 {lo,hi}, %0;\n\t"
        "max.f32 lo, lo, 0f00000000;\n\t"
        "max.f32 hi, hi, 0f00000000;\n\t"
        "mov.b64 %0, {lo,hi};\n\t"
        "}" : "+l"(x));
    return x;
}

__global__ void __launch_bounds__(THREADS, 4) convkb_kernel(
    const float* __restrict__ h,
    const float* __restrict__ g,
    const int*   __restrict__ edge_idx,   // [2, E] int32
    const int*   __restrict__ edge_type,  // [E]    int32
    const float* __restrict__ conv_w,     // [C,3]
    const float* __restrict__ conv_b,     // [C]
    const float* __restrict__ lin_w,      // [C*D]
    const float* __restrict__ lin_b,      // [1]
    float* __restrict__ out,              // [E]
    int n_edges)
{
    __shared__ float4 s_lin[C * D / 4];              // 16 KB, [c*32 + j]
    __shared__ ull    s_convp[C * 4];                // {w0,w0},{w1,w1},{w2,w2},{b,b}
    __shared__ float  s_part[2][PAIRS_PER_BLOCK][EB]; // double-buffered pair exchange

    const int tid = threadIdx.x;

    const float4* lw4 = reinterpret_cast<const float4*>(lin_w);
    #pragma unroll 4
    for (int i = tid; i < C * D / 4; i += THREADS) s_lin[i] = lw4[i];
    if (tid < C) {
        float w0 = conv_w[tid * 3 + 0];
        float w1 = conv_w[tid * 3 + 1];
        float w2 = conv_w[tid * 3 + 2];
        float cb = conv_b[tid];
        s_convp[tid * 4 + 0] = pack2(w0, w0);
        s_convp[tid * 4 + 1] = pack2(w1, w1);
        s_convp[tid * 4 + 2] = pack2(w2, w2);
        s_convp[tid * 4 + 3] = pack2(cb, cb);
    }
    __syncthreads();

    const float bias_out = lin_b[0];

    const unsigned s_lin_base  = (unsigned)__cvta_generic_to_shared(s_lin);
    const unsigned s_conv_base = (unsigned)__cvta_generic_to_shared(s_convp);

    const int warp = tid >> 5;
    const int lane = tid & 31;
    const int pair = warp >> 1;       // 0..3
    const int p    = warp & 1;        // d-half
    const int pair_global = blockIdx.x * PAIRS_PER_BLOCK + pair;
    const int n_pairs = gridDim.x * PAIRS_PER_BLOCK;

    // This warp's float offset within an embedding row (2 floats, 8B aligned)
    const int lane_off = p * 64 + lane * 2;
    // lw base: byte offset c*512 + p*256 + lane*8
    const unsigned lw_base = s_lin_base + (unsigned)(p * 256 + lane * 8);

    int buf = 0;
    for (int e0 = pair_global * EB; e0 < n_edges; e0 += n_pairs * EB, buf ^= 1) {
        // --- indices for 4 edges (clamped) ---
        ull a[EB], b[EB], r[EB];
        #pragma unroll
        for (int k = 0; k < EB; k++) {
            int e = e0 + k; if (e >= n_edges) e = n_edges - 1;
            int row = edge_idx[e];
            int col = edge_idx[n_edges + e];
            int typ = edge_type[e];
            a[k] = *reinterpret_cast<const ull*>(h + (size_t)row * D + lane_off);
            b[k] = *reinterpret_cast<const ull*>(h + (size_t)col * D + lane_off);
            r[k] = *reinterpret_cast<const ull*>(g + (size_t)typ * D + lane_off);
        }

        ull acc[EB];
        #pragma unroll
        for (int k = 0; k < EB; k++) acc[k] = 0ULL;

        // --- channel loop: weights loaded once per c, used for 4 edges ---
        #pragma unroll 8
        for (int c = 0; c < C; c++) {
            ull w00, w11, w22, bb, lw;
            unsigned ca = s_conv_base + c * 32;
            asm("ld.shared.v2.u64 {%0,%1},[%2];" : "=l"(w00), "=l"(w11) : "r"(ca));
            asm("ld.shared.v2.u64 {%0,%1},[%2];" : "=l"(w22), "=l"(bb)  : "r"(ca + 16));
            asm("ld.shared.u64 %0,[%1];" : "=l"(lw) : "r"(lw_base + (unsigned)(c * 512)));

            #pragma unroll
            for (int k = 0; k < EB; k++) {
                ull t = fma2(w22, r[k], bb);
                t = fma2(w11, b[k], t);
                t = fma2(w00, a[k], t);
                t = relu2(t);
                acc[k] = fma2(t, lw, acc[k]);
            }
        }

        // --- per-edge reduction: halves + lanes (all lanes end with the sum) ---
        float sred[EB];
        #pragma unroll
        for (int k = 0; k < EB; k++) {
            float2 u = unpack2(acc[k]);
            float s = u.x + u.y;
            #pragma unroll
            for (int o = 16; o > 0; o >>= 1)
                s += __shfl_xor_sync(0xFFFFFFFFu, s, o);
            sred[k] = s;
        }

        // odd warp publishes its partials; even warp combines + stores
        if (p == 1 && lane == 0) {
            #pragma unroll
            for (int k = 0; k < EB; k++) s_part[buf][pair][k] = sred[k];
        }
        asm volatile("bar.sync %0, %1;" :: "r"(pair + 1), "r"(64) : "memory");

        if (p == 0 && lane == 0) {
            float o0 = sred[0] + s_part[buf][pair][0] + bias_out;
            float o1 = sred[1] + s_part[buf][pair][1] + bias_out;
            float o2 = sred[2] + s_part[buf][pair][2] + bias_out;
            float o3 = sred[3] + s_part[buf][pair][3] + bias_out;
            if (e0 + 3 < n_edges) {
                *reinterpret_cast<float4*>(out + e0) = make_float4(o0, o1, o2, o3);
            } else {
                if (e0 + 0 < n_edges) out[e0 + 0] = o0;
                if (e0 + 1 < n_edges) out[e0 + 1] = o1;
                if (e0 + 2 < n_edges) out[e0 + 2] = o2;
                if (e0 + 3 < n_edges) out[e0 + 3] = o3;
            }
        }
    }
}

extern "C" void kernel_launch(void* const* d_in, const int* in_sizes, int n_in,
                              void* d_out, int out_size) {
    const float* h         = (const float*)d_in[0];
    const float* g         = (const float*)d_in[1];
    const int*   edge_idx  = (const int*)d_in[2];
    const int*   edge_type = (const int*)d_in[3];
    const float* conv_w    = (const float*)d_in[4];
    const float* conv_b    = (const float*)d_in[5];
    const float* lin_w     = (const float*)d_in[6];
    const float* lin_b     = (const float*)d_in[7];
    float*       out       = (float*)d_out;

    const int n_edges = in_sizes[3];  // edge_type element count == E

    // Balance: edges per grid-iteration = blocks * PAIRS * EB. Choose the
    // iteration count so blocks <= MAX_BLOCKS and every pair runs the same
    // number of full iterations (kills the fractional-tail idle wave).
    const int per_block = PAIRS_PER_BLOCK * EB;  // 16
    int iters = (n_edges + MAX_BLOCKS * per_block - 1) / (MAX_BLOCKS * per_block);
    int nblocks = (n_edges + per_block * iters - 1) / (per_block * iters);
    if (nblocks < 1) nblocks = 1;

    convkb_kernel<<<nblocks, THREADS>>>(h, g, edge_idx, edge_type,
                                        conv_w, conv_b, lin_w, lin_b,
                                        out, n_edges);
}